// round 12
// baseline (speedup 1.0000x reference)
#include <cuda_runtime.h>
#include <cstdint>

// Problem constants: B=64, MEL_MAX=2000, TEXT_MAX=256, g=0.2
#define BATCH   64
#define MEL_MAX 2000
#define TXT_MAX 256
#define A_COEF  12.5f            // 1/(2 g^2)

#define SLABS   16               // t-slabs per batch
#define SLAB    125              // rows per slab (16*125 = 2000)
#define NBLK    (SLABS * BATCH)  // 1024 blocks
#define NTHR    256              // 8 warps

typedef unsigned long long u64;

// Scratch (__device__ globals — no allocation allowed)
__device__ double       g_block[NBLK];
__device__ unsigned int g_count = 0;

// ---- packed f32x2 helpers (Blackwell) ----
__device__ __forceinline__ u64 pk2(float lo, float hi) {
    u64 r; asm("mov.b64 %0,{%1,%2};" : "=l"(r) : "f"(lo), "f"(hi)); return r;
}
__device__ __forceinline__ void unpk2(u64 a, float& lo, float& hi) {
    asm("mov.b64 {%0,%1},%2;" : "=f"(lo), "=f"(hi) : "l"(a));
}
__device__ __forceinline__ u64 mul2(u64 a, u64 b) {
    u64 r; asm("mul.rn.f32x2 %0,%1,%2;" : "=l"(r) : "l"(a), "l"(b)); return r;
}
__device__ __forceinline__ u64 add2(u64 a, u64 b) {
    u64 r; asm("add.rn.f32x2 %0,%1,%2;" : "=l"(r) : "l"(a), "l"(b)); return r;
}
__device__ __forceinline__ u64 fma2(u64 a, u64 b, u64 c) {
    u64 r; asm("fma.rn.f32x2 %0,%1,%2,%3;" : "=l"(r) : "l"(a), "l"(b), "l"(c)); return r;
}

// ---------------------------------------------------------------------------
// Fused kernel, slab-balanced, DYNAMIC LANE PACKING:
//   L = ceil(tl/8) lanes per row, rounded to 2^s; R = 32>>s rows per pass.
//   lane -> row t + (lane>>s), columns 8*(lane & (2^s -1)) .. +7.
//   Block (x,b) owns t in [125x, min(125(x+1),ml)); warp w base row =
//   tbase + w*R; pass stride = 8R rows. Gaussian recurrent in both axes
//   (no MUFU in the loop). Last block (atomic ticket) finalizes.
// ---------------------------------------------------------------------------
__global__ __launch_bounds__(NTHR, 5) void fused_kernel(
    const float* __restrict__ pred,
    const int*   __restrict__ tlen,
    const int*   __restrict__ mlen,
    float*       __restrict__ out)
{
    const int lane = threadIdx.x & 31;
    const int wid  = threadIdx.x >> 5;
    const int b    = blockIdx.y;
    const int x    = blockIdx.x;

    const int ml    = __ldg(&mlen[b]);
    const int tbase = x * SLAB;

    u64 sP = 0, sE = 0;   // packed accumulators: sum p, sum E*p

    if (tbase < ml) {
        const int tl   = __ldg(&tlen[b]);
        const int tend = (tbase + SLAB < ml) ? tbase + SLAB : ml;

        // ---- dynamic lane layout ----
        const int L = (tl + 7) >> 3;                      // lanes per row 1..32
        int s = (L <= 1) ? 0 : (32 - __clz(L - 1));       // ceil(log2(L))
        const int R      = 32 >> s;                       // rows per pass
        const int sub    = lane & ((1 << s) - 1);         // lane within row
        const int g      = lane >> s;                     // row offset in pass
        const int stride = 8 * R;                         // rows per pass step

        // ---- loop-invariant constants ----
        const float inv_tl = 1.0f / (float)tl;
        const float inv_ml = 1.0f / (float)ml;
        const int   n0     = sub * 8;
        const float alpha0 = (float)n0 * inv_tl;
        const float ca     = 2.0f * A_COEF * inv_tl * inv_ml;
        const float cb     = -A_COEF * inv_tl * inv_tl * (float)(2 * n0 + 1);
        const float q2     = __expf(-2.0f * A_COEF * inv_tl * inv_tl);
        const float q2sq   = q2 * q2;
        const float q8     = q2sq * q2sq;
        const u64   Q4     = pk2(q8, q8);

        int count = tl - n0; if (count < 0) count = 0; if (count > 8) count = 8;
        const bool pred_lo = (count > 0);
        const bool pred_hi = (count > 4);
        const u64 mk0 = pk2(count > 0 ? 1.0f : 0.0f, count > 1 ? 1.0f : 0.0f);
        const u64 mk1 = pk2(count > 2 ? 1.0f : 0.0f, count > 3 ? 1.0f : 0.0f);
        const u64 mk2 = pk2(count > 4 ? 1.0f : 0.0f, count > 5 ? 1.0f : 0.0f);
        const u64 mk3 = pk2(count > 6 ? 1.0f : 0.0f, count > 7 ? 1.0f : 0.0f);

        // ---- per-lane t-direction seed recurrence (stride = 8R) ----
        const int   tw  = tbase + wid * R;    // warp base row (g=0 lane)
        const int   t0  = tw + g;             // this lane's first row
        const float di  = (float)stride * inv_ml;
        const float u0v = alpha0 - (float)t0 * inv_ml;
        float S  = __expf(-2.0f * A_COEF * di * di);
        float E0 = __expf(-A_COEF * u0v * u0v);
        float rr = __expf(2.0f * A_COEF * di * u0v - A_COEF * di * di);
        float m0 = __expf(fmaf(ca, (float)t0, cb));
        float RM = __expf((float)stride * ca);
        if (!pred_lo) { E0 = 0.0f; rr = 0.0f; m0 = 0.0f; RM = 0.0f; }

        // column chain for one pass (packed even/odd recurrence).
        // E0v/m0v MUST already be SEL-zeroed for invalid rows.
        auto chain = [&](float E0v, float m0v, ulonglong2 lo, ulonglong2 hi) {
            const float ms = m0v * m0v;
            const float m2 = ms * q2;
            u64 E2 = pk2(E0v, E0v * m0v);
            u64 M2 = pk2(m2, m2 * q2sq);
            u64 mp;
            mp = mul2(lo.x, mk0); sP = add2(sP, mp); sE = fma2(E2, mp, sE);
            E2 = mul2(E2, M2); M2 = mul2(M2, Q4);
            mp = mul2(lo.y, mk1); sP = add2(sP, mp); sE = fma2(E2, mp, sE);
            E2 = mul2(E2, M2); M2 = mul2(M2, Q4);
            mp = mul2(hi.x, mk2); sP = add2(sP, mp); sE = fma2(E2, mp, sE);
            E2 = mul2(E2, M2);
            mp = mul2(hi.y, mk3); sP = add2(sP, mp); sE = fma2(E2, mp, sE);
        };

        const float* rowp = pred + (size_t)b * (MEL_MAX * TXT_MAX)
                                 + (size_t)t0 * TXT_MAX + n0;
        const size_t pstep = (size_t)stride * TXT_MAX;
        int t = tw;

        // ---- main loop: two passes per iteration ----
        for (; t + stride < tend; t += 2 * stride, rowp += 2 * pstep) {
            const bool rv0 = (t + g < tend);               // pass 0 row valid
            const bool rv1 = (t + stride + g < tend);      // pass 1 row valid

            ulonglong2 a0; a0.x = 0; a0.y = 0;
            ulonglong2 b0; b0.x = 0; b0.y = 0;
            ulonglong2 a1; a1.x = 0; a1.y = 0;
            ulonglong2 b1; b1.x = 0; b1.y = 0;
            const float* r1 = rowp + pstep;
            if (pred_lo && rv0) a0 = *(const ulonglong2*)rowp;
            if (pred_lo && rv1) a1 = *(const ulonglong2*)r1;
            if (pred_hi && rv0) b0 = *(const ulonglong2*)(rowp + 4);
            if (pred_hi && rv1) b1 = *(const ulonglong2*)(r1 + 4);

            const float E0a = rv0 ? E0 : 0.0f;
            const float m0a = rv0 ? m0 : 0.0f;
            E0 *= rr; rr *= S; m0 *= RM;
            const float E0b = rv1 ? E0 : 0.0f;
            const float m0b = rv1 ? m0 : 0.0f;
            E0 *= rr; rr *= S; m0 *= RM;

            chain(E0a, m0a, a0, b0);
            chain(E0b, m0b, a1, b1);
        }

        // ---- tail: at most one pass ----
        if (t < tend) {
            const bool rv = (t + g < tend);
            ulonglong2 a0; a0.x = 0; a0.y = 0;
            ulonglong2 b0; b0.x = 0; b0.y = 0;
            if (pred_lo && rv) a0 = *(const ulonglong2*)rowp;
            if (pred_hi && rv) b0 = *(const ulonglong2*)(rowp + 4);
            const float E0a = rv ? E0 : 0.0f;
            const float m0a = rv ? m0 : 0.0f;
            chain(E0a, m0a, a0, b0);
        }
    }

    // ---- combine: loss = sum p - sum E p ----
    float x0, x1, y0, y1;
    unpk2(sP, x0, x1);
    unpk2(sE, y0, y1);
    float tot = (x0 + x1) - (y0 + y1);

    #pragma unroll
    for (int o = 16; o > 0; o >>= 1)
        tot += __shfl_xor_sync(0xFFFFFFFFu, tot, o);

    __shared__ double wsum[8];
    if (lane == 0) wsum[wid] = (double)tot;
    __syncthreads();

    __shared__ bool amLast;
    const int bid = blockIdx.y * SLABS + blockIdx.x;
    if (threadIdx.x == 0) {
        double sacc = 0.0;
        #pragma unroll
        for (int k = 0; k < 8; k++) sacc += wsum[k];
        g_block[bid] = sacc;
        __threadfence();
        amLast = (atomicAdd(&g_count, 1u) == NBLK - 1);
    }
    __syncthreads();

    // ---- last block: final reduction + normalizer ----
    if (amLast) {
        __threadfence();
        double sv = 0.0;
        for (int k = threadIdx.x; k < NBLK; k += NTHR)
            sv += __ldcg(&g_block[k]);
        double sa = 0.0;
        if (threadIdx.x < BATCH)
            sa = (double)__ldg(&tlen[threadIdx.x]) * (double)__ldg(&mlen[threadIdx.x]);

        #pragma unroll
        for (int o = 16; o > 0; o >>= 1) {
            sv += __shfl_xor_sync(0xFFFFFFFFu, sv, o);
            sa += __shfl_xor_sync(0xFFFFFFFFu, sa, o);
        }

        __shared__ double fv[8], fa[8];
        if (lane == 0) { fv[wid] = sv; fa[wid] = sa; }
        __syncthreads();

        if (threadIdx.x == 0) {
            double tv = 0.0, ta = 0.0;
            #pragma unroll
            for (int k = 0; k < 8; k++) { tv += fv[k]; ta += fa[k]; }
            out[0] = (float)(tv / ta);   // attention_weight = 1.0
            g_count = 0;                 // reset for next graph replay
        }
    }
}

// ---------------------------------------------------------------------------
// Inputs (metadata order): targets (unused), predictions, text_lengths,
// mel_lengths. Output: single float.
// ---------------------------------------------------------------------------
extern "C" void kernel_launch(void* const* d_in, const int* in_sizes, int n_in,
                              void* d_out, int out_size)
{
    (void)in_sizes; (void)n_in; (void)out_size;
    const float* pred = (const float*)d_in[1];
    const int*   tlen = (const int*)d_in[2];
    const int*   mlen = (const int*)d_in[3];
    float*       out  = (float*)d_out;

    dim3 grid(SLABS, BATCH);
    fused_kernel<<<grid, NTHR>>>(pred, tlen, mlen, out);
}